// round 4
// baseline (speedup 1.0000x reference)
#include <cuda_runtime.h>
#include <math.h>

#define UNQ   256
#define DIM   1024
#define NT    16
#define BATCH 16384

static __device__ float g_X[UNQ*DIM];
static __device__ float g_H[NT*UNQ*DIM];
static __device__ float g_Y[NT*UNQ*DIM];
static __device__ float g_HS[UNQ*DIM];
static __device__ int   g_cnt[NT];
static __device__ int   g_rows[NT*UNQ];
static __device__ float g_gate[NT*UNQ];
static __device__ int   g_pairs[UNQ*4];
static __device__ float g_table[UNQ*11];

__device__ __forceinline__ float gelu_f(float x) {
    return 0.5f * x * (1.0f + erff(x * 0.70710678118654752f));
}

__device__ __forceinline__ float block_reduce_sum_256(float v, float* red) {
    int tid = threadIdx.x;
    red[tid] = v;
    __syncthreads();
    #pragma unroll
    for (int s = 128; s > 0; s >>= 1) {
        if (tid < s) red[tid] += red[tid + s];
        __syncthreads();
    }
    float r = red[0];
    __syncthreads();
    return r;
}

// ---------------------------------------------------------------------------
// Encode: fourier(a),fourier(b) -> @Win + bias -> LN -> GELU, for 256 uniques
// (block 0 also zeroes the tile counters for layer 0's router)
// ---------------------------------------------------------------------------
__global__ void encode_kernel(const float* __restrict__ Win, const float* __restrict__ bin_,
                              const float* __restrict__ gin, const float* __restrict__ bln) {
    int u = blockIdx.x, tid = threadIdx.x;
    if (u == 0 && tid < NT) g_cnt[tid] = 0;
    __shared__ float feat[32];
    __shared__ float red[256];
    if (tid < 32) {
        int which  = tid >> 4;
        int idx    = tid & 15;
        int fi     = idx & 7;
        int is_cos = (idx >> 3) & 1;
        int val    = which ? (u & 15) : (u >> 4);
        float xn   = (float)val * 0.39269908169872414f;   // fp32(2*pi/16)
        float ang  = xn * exp2f((float)fi);
        double dd  = (double)ang;
        feat[tid]  = (float)(is_cos ? cos(dd) : sin(dd));
    }
    __syncthreads();
    float v[4];
    #pragma unroll
    for (int j = 0; j < 4; ++j) {
        int d = tid + 256*j;
        float acc = bin_[d];
        #pragma unroll
        for (int f = 0; f < 32; ++f) acc += feat[f] * Win[f*DIM + d];
        v[j] = acc;
    }
    float s = block_reduce_sum_256(v[0]+v[1]+v[2]+v[3], red);
    float m = s * (1.0f/DIM);
    float s2l = 0.f;
    #pragma unroll
    for (int j = 0; j < 4; ++j) { float t = v[j]-m; s2l += t*t; }
    float s2 = block_reduce_sum_256(s2l, red);
    float rs = rsqrtf(s2*(1.0f/DIM) + 1e-5f);
    #pragma unroll
    for (int j = 0; j < 4; ++j) {
        int d = tid + 256*j;
        float y = (v[j]-m)*rs*gin[d] + bln[d];
        g_X[u*DIM + d] = gelu_f(y);
    }
}

// ---------------------------------------------------------------------------
// Router: softmax(x @ Wr) -> top-4 -> per-tile compacted (row, gate) lists
// ---------------------------------------------------------------------------
__global__ void router_kernel(const float* __restrict__ Wr) {
    int r = blockIdx.x, tid = threadIdx.x;
    __shared__ float part[256];
    int t = tid & 15, seg = tid >> 4;
    const float* x = g_X + r*DIM;
    float p = 0.f;
    int base = seg*64;
    #pragma unroll 8
    for (int j = 0; j < 64; ++j) p += x[base+j] * Wr[(base+j)*NT + t];
    part[tid] = p;
    __syncthreads();
    if (tid < 16) {
        float lg = 0.f;
        #pragma unroll
        for (int s = 0; s < 16; ++s) lg += part[tid + (s<<4)];
        part[tid] = lg;
    }
    __syncthreads();
    if (tid == 0) {
        float lg[16], mx = -1e30f;
        #pragma unroll
        for (int i = 0; i < 16; ++i) { lg[i] = part[i]; mx = fmaxf(mx, lg[i]); }
        float pe[16], sum = 0.f;
        #pragma unroll
        for (int i = 0; i < 16; ++i) { pe[i] = expf(lg[i]-mx); sum += pe[i]; }
        float inv = 1.0f/sum;
        unsigned used = 0;
        for (int s = 0; s < 4; ++s) {
            int best = -1; float bv = -1e30f;
            #pragma unroll
            for (int i = 0; i < 16; ++i)
                if (!((used>>i)&1) && pe[i] > bv) { bv = pe[i]; best = i; }
            used |= 1u << best;
            int pos = atomicAdd(&g_cnt[best], 1);
            g_rows[best*UNQ + pos] = r;
            g_gate[best*UNQ + pos] = bv*inv;
            g_pairs[r*4 + s] = best*UNQ + pos;
        }
    }
}

// ---------------------------------------------------------------------------
// FFN GEMM v2: 64x128 block tile, 8x4 microtile, K=16 double-buffered smem
// MODE 0: H[p] = gelu(X[row] @ W1[t] + b1[t])     (gathered rows)
// MODE 1: Y[p] = gate[p] * (H[p] @ W2[t] + b2[t]) (contiguous rows)
// ---------------------------------------------------------------------------
template<int MODE>
__global__ void __launch_bounds__(256, 3) ffn_kernel(const float* __restrict__ W,
                                                     const float* __restrict__ bias) {
    int t  = blockIdx.z, rc = blockIdx.y, cc = blockIdx.x;
    int cnt = g_cnt[t];
    if (rc*64 >= cnt) return;

    W += (size_t)t*DIM*DIM;

    __shared__ float Xs[2][64][16];
    __shared__ float Ws[2][16][128];
    __shared__ int   rows_s[64];
    __shared__ float gate_s[64];

    int tid = threadIdx.x;
    if (tid < 64) {
        int idx = rc*64 + tid;
        int ci  = (idx < cnt) ? idx : (cnt-1);
        if (MODE == 0) rows_s[tid] = g_rows[t*UNQ + ci];
        else {
            rows_s[tid] = t*UNQ + rc*64 + tid;
            gate_s[tid] = (idx < cnt) ? g_gate[t*UNQ + idx] : 0.f;
        }
    }
    __syncthreads();

    const float* src = (MODE == 0) ? g_X : g_H;
    int rg = tid >> 5;          // warp id 0..7 -> rows rg*8 .. rg*8+7
    int cg = tid & 31;          // cols cg*4 .. cg*4+3
    int c0 = cc*128;

    // staging maps
    int xr  = tid >> 2;         // 0..63 : X row
    int xkq = tid & 3;          // float4 within 16-k row
    const float* xsrc = src + (size_t)rows_s[xr]*DIM + xkq*4;
    int wk0 = tid >> 5, wc0 = tid & 31;        // e = tid
    int wk1 = (tid+256) >> 5, wc1 = tid & 31;  // e = tid+256

    float acc[8][4];
    #pragma unroll
    for (int i = 0; i < 8; ++i)
        #pragma unroll
        for (int j = 0; j < 4; ++j) acc[i][j] = 0.f;

    // prologue: load tile 0
    float4 xv  = *(const float4*)(xsrc);
    float4 wv0 = *(const float4*)&W[(size_t)wk0*DIM + c0 + wc0*4];
    float4 wv1 = *(const float4*)&W[(size_t)wk1*DIM + c0 + wc1*4];
    *(float4*)&Xs[0][xr][xkq*4] = xv;
    *(float4*)&Ws[0][wk0][wc0*4] = wv0;
    *(float4*)&Ws[0][wk1][wc1*4] = wv1;
    __syncthreads();

    int buf = 0;
    for (int k0 = 0; k0 < DIM; k0 += 16) {
        int nk = k0 + 16;
        if (nk < DIM) {
            xv  = *(const float4*)(xsrc + nk);
            wv0 = *(const float4*)&W[(size_t)(nk+wk0)*DIM + c0 + wc0*4];
            wv1 = *(const float4*)&W[(size_t)(nk+wk1)*DIM + c0 + wc1*4];
        }
        const float (*Xc)[16]  = Xs[buf];
        const float (*Wc)[128] = Ws[buf];
        #pragma unroll
        for (int k = 0; k < 16; ++k) {
            float4 bv = *(const float4*)&Wc[k][cg*4];
            #pragma unroll
            for (int i = 0; i < 8; ++i) {
                float a = Xc[rg*8+i][k];
                acc[i][0] += a*bv.x; acc[i][1] += a*bv.y;
                acc[i][2] += a*bv.z; acc[i][3] += a*bv.w;
            }
        }
        if (nk < DIM) {
            *(float4*)&Xs[buf^1][xr][xkq*4]  = xv;
            *(float4*)&Ws[buf^1][wk0][wc0*4] = wv0;
            *(float4*)&Ws[buf^1][wk1][wc1*4] = wv1;
        }
        __syncthreads();
        buf ^= 1;
    }

    int pbase = t*UNQ + rc*64;
    float bvals[4];
    #pragma unroll
    for (int j = 0; j < 4; ++j) bvals[j] = bias[t*DIM + c0 + cg*4 + j];

    #pragma unroll
    for (int i = 0; i < 8; ++i) {
        int lr = rg*8 + i;
        float v0 = acc[i][0]+bvals[0], v1 = acc[i][1]+bvals[1];
        float v2 = acc[i][2]+bvals[2], v3 = acc[i][3]+bvals[3];
        float4 o;
        if (MODE == 0) {
            o.x = gelu_f(v0); o.y = gelu_f(v1); o.z = gelu_f(v2); o.w = gelu_f(v3);
            *(float4*)&g_H[(size_t)(pbase+lr)*DIM + c0 + cg*4] = o;
        } else {
            float gt = gate_s[lr];
            o.x = v0*gt; o.y = v1*gt; o.z = v2*gt; o.w = v3*gt;
            *(float4*)&g_Y[(size_t)(pbase+lr)*DIM + c0 + cg*4] = o;
        }
    }
}

// ---------------------------------------------------------------------------
// Combine: x = LN(x + sum of the row's 4 gated expert outputs)
// (block 0 also zeroes tile counters for the NEXT layer's router)
// ---------------------------------------------------------------------------
__global__ void combine_kernel(const float* __restrict__ gl, const float* __restrict__ bl) {
    int r = blockIdx.x, tid = threadIdx.x;
    __shared__ float red[256];
    int p0 = g_pairs[r*4+0], p1 = g_pairs[r*4+1];
    int p2 = g_pairs[r*4+2], p3 = g_pairs[r*4+3];
    float v[4];
    #pragma unroll
    for (int j = 0; j < 4; ++j) {
        int d = tid + 256*j;
        v[j] = g_X[r*DIM+d]
             + g_Y[(size_t)p0*DIM+d] + g_Y[(size_t)p1*DIM+d]
             + g_Y[(size_t)p2*DIM+d] + g_Y[(size_t)p3*DIM+d];
    }
    if (r == 0 && tid < NT) g_cnt[tid] = 0;   // reset for next router
    float s = block_reduce_sum_256(v[0]+v[1]+v[2]+v[3], red);
    float m = s * (1.0f/DIM);
    float s2l = 0.f;
    #pragma unroll
    for (int j = 0; j < 4; ++j) { float t = v[j]-m; s2l += t*t; }
    float s2 = block_reduce_sum_256(s2l, red);
    float rs = rsqrtf(s2*(1.0f/DIM) + 1e-5f);
    #pragma unroll
    for (int j = 0; j < 4; ++j) {
        int d = tid + 256*j;
        g_X[r*DIM+d] = (v[j]-m)*rs*gl[d] + bl[d];
    }
}

// ---------------------------------------------------------------------------
// Heads stage 1 as tiled GEMM: g_HS[u, 0:512]  = gelu(x @ Ws1 + bs1)
//                              g_HS[u, 512:1024]= gelu(x @ Wd1 + bd1)
// 32x128 tile, 4x4 microtile. grid (8 cc, 8 rc).
// ---------------------------------------------------------------------------
__global__ void headsA_kernel(const float* __restrict__ Ws1, const float* __restrict__ bs1,
                              const float* __restrict__ Wd1, const float* __restrict__ bd1) {
    int cc = blockIdx.x, rc = blockIdx.y;
    const float* W  = (cc < 4) ? Ws1 : Wd1;
    const float* bi = (cc < 4) ? bs1 : bd1;
    int c0     = (cc & 3) * 128;
    int outoff = (cc < 4) ? 0 : 512;

    __shared__ float Xs[32][32];
    __shared__ float Ws_[32][128];

    int tid = threadIdx.x;
    int rg = tid >> 5, cg = tid & 31;
    float acc[4][4];
    #pragma unroll
    for (int i = 0; i < 4; ++i)
        #pragma unroll
        for (int j = 0; j < 4; ++j) acc[i][j] = 0.f;

    int li = tid >> 3, lkv = tid & 7;

    for (int k0 = 0; k0 < DIM; k0 += 32) {
        *(float4*)&Xs[li][lkv*4] =
            *(const float4*)&g_X[(size_t)(rc*32+li)*DIM + k0 + lkv*4];
        #pragma unroll
        for (int q = 0; q < 4; ++q) {
            int e = tid + q*256;
            int k = e >> 5, cv = e & 31;
            *(float4*)&Ws_[k][cv*4] =
                *(const float4*)&W[(size_t)(k0+k)*512 + c0 + cv*4];
        }
        __syncthreads();
        #pragma unroll
        for (int k = 0; k < 32; ++k) {
            float a0 = Xs[rg*4+0][k], a1 = Xs[rg*4+1][k];
            float a2 = Xs[rg*4+2][k], a3 = Xs[rg*4+3][k];
            float4 bv = *(const float4*)&Ws_[k][cg*4];
            acc[0][0] += a0*bv.x; acc[0][1] += a0*bv.y; acc[0][2] += a0*bv.z; acc[0][3] += a0*bv.w;
            acc[1][0] += a1*bv.x; acc[1][1] += a1*bv.y; acc[1][2] += a1*bv.z; acc[1][3] += a1*bv.w;
            acc[2][0] += a2*bv.x; acc[2][1] += a2*bv.y; acc[2][2] += a2*bv.z; acc[2][3] += a2*bv.w;
            acc[3][0] += a3*bv.x; acc[3][1] += a3*bv.y; acc[3][2] += a3*bv.z; acc[3][3] += a3*bv.w;
        }
        __syncthreads();
    }

    float bvals[4];
    #pragma unroll
    for (int j = 0; j < 4; ++j) bvals[j] = bi[c0 + cg*4 + j];
    #pragma unroll
    for (int i = 0; i < 4; ++i) {
        int row = rc*32 + rg*4 + i;
        float4 o;
        o.x = gelu_f(acc[i][0]+bvals[0]);
        o.y = gelu_f(acc[i][1]+bvals[1]);
        o.z = gelu_f(acc[i][2]+bvals[2]);
        o.w = gelu_f(acc[i][3]+bvals[3]);
        *(float4*)&g_HS[(size_t)row*DIM + outoff + c0 + cg*4] = o;
    }
}

// ---------------------------------------------------------------------------
// Heads stage 2: table[u] = [hs @ Ws2 + bs2 , hd @ Wd2 + bd2]
// ---------------------------------------------------------------------------
__global__ void headsB_kernel(const float* __restrict__ Ws2, const float* __restrict__ bs2,
                              const float* __restrict__ Wd2, const float* __restrict__ bd2) {
    int u = blockIdx.x, tid = threadIdx.x;
    __shared__ float h[DIM];
    #pragma unroll
    for (int j = 0; j < 4; ++j) h[tid+256*j] = g_HS[(size_t)u*DIM + tid + 256*j];
    __syncthreads();
    if (tid < 5) {
        float o = bs2[tid];
        for (int k = 0; k < 512; ++k) o += h[k]*Ws2[k*5 + tid];
        g_table[u*11 + tid] = o;
    } else if (tid < 11) {
        int j = tid - 5;
        float o = bd2[j];
        for (int k = 0; k < 512; ++k) o += h[512+k]*Wd2[k*6 + j];
        g_table[u*11 + tid] = o;
    }
}

// ---------------------------------------------------------------------------
// Scatter table rows back to the full batch
// ---------------------------------------------------------------------------
__global__ void scatter_kernel(const int* __restrict__ a, const int* __restrict__ b,
                               float* __restrict__ out) {
    int idx = blockIdx.x*blockDim.x + threadIdx.x;
    if (idx >= BATCH*11) return;
    int i = idx / 11;
    int j = idx - i*11;
    int u = a[i]*16 + b[i];
    out[idx] = g_table[u*11 + j];
}

// ---------------------------------------------------------------------------
extern "C" void kernel_launch(void* const* d_in, const int* in_sizes, int n_in,
                              void* d_out, int out_size) {
    const int*   a    = (const int*)  d_in[0];
    const int*   b    = (const int*)  d_in[1];
    const float* Win  = (const float*)d_in[2];
    const float* bin_ = (const float*)d_in[3];
    const float* g_in = (const float*)d_in[4];
    const float* bln  = (const float*)d_in[5];
    const float* Wr   = (const float*)d_in[6];
    const float* W1   = (const float*)d_in[7];
    const float* b1   = (const float*)d_in[8];
    const float* W2   = (const float*)d_in[9];
    const float* b2   = (const float*)d_in[10];
    const float* g_l  = (const float*)d_in[11];
    const float* b_l  = (const float*)d_in[12];
    const float* Ws1  = (const float*)d_in[13];
    const float* bs1  = (const float*)d_in[14];
    const float* Ws2  = (const float*)d_in[15];
    const float* bs2  = (const float*)d_in[16];
    const float* Wd1  = (const float*)d_in[17];
    const float* bd1  = (const float*)d_in[18];
    const float* Wd2  = (const float*)d_in[19];
    const float* bd2  = (const float*)d_in[20];
    float* out = (float*)d_out;

    encode_kernel<<<UNQ, 256>>>(Win, bin_, g_in, bln);
    for (int l = 0; l < 3; ++l) {
        router_kernel<<<UNQ, 256>>>(Wr + (size_t)l*DIM*NT);
        ffn_kernel<0><<<dim3(8, 4, 16), 256>>>(W1 + (size_t)l*NT*DIM*DIM,
                                               b1 + (size_t)l*NT*DIM);
        ffn_kernel<1><<<dim3(8, 4, 16), 256>>>(W2 + (size_t)l*NT*DIM*DIM,
                                               b2 + (size_t)l*NT*DIM);
        combine_kernel<<<UNQ, 256>>>(g_l + (size_t)l*DIM, b_l + (size_t)l*DIM);
    }
    headsA_kernel<<<dim3(8, 8), 256>>>(Ws1, bs1, Wd1, bd1);
    headsB_kernel<<<UNQ, 256>>>(Ws2, bs2, Wd2, bd2);
    scatter_kernel<<<(BATCH*11 + 255)/256, 256>>>(a, b, out);
}

// round 7
// speedup vs baseline: 3.3669x; 3.3669x over previous
#include <cuda_runtime.h>
#include <math.h>

#define UNQ   256
#define DIM   1024
#define NT    16
#define BATCH 16384

static __device__ float g_X[UNQ*DIM];
static __device__ float g_H[NT*UNQ*DIM];
static __device__ float g_Y[NT*UNQ*DIM];
static __device__ float g_HS[UNQ*DIM];
static __device__ int   g_cnt[NT];
static __device__ int   g_rows[NT*UNQ];
static __device__ float g_gate[NT*UNQ];
static __device__ int   g_pairs[UNQ*4];
static __device__ float g_table[UNQ*11];

__device__ __forceinline__ float gelu_f(float x) {
    return 0.5f * x * (1.0f + erff(x * 0.70710678118654752f));
}

__device__ __forceinline__ void cp16(void* smem, const void* gmem) {
    unsigned s = (unsigned)__cvta_generic_to_shared(smem);
    asm volatile("cp.async.cg.shared.global [%0], [%1], 16;\n" :: "r"(s), "l"(gmem));
}
__device__ __forceinline__ void cp_commit() {
    asm volatile("cp.async.commit_group;\n");
}

__device__ __forceinline__ float block_reduce_sum_256(float v, float* red) {
    int tid = threadIdx.x;
    red[tid] = v;
    __syncthreads();
    #pragma unroll
    for (int s = 128; s > 0; s >>= 1) {
        if (tid < s) red[tid] += red[tid + s];
        __syncthreads();
    }
    float r = red[0];
    __syncthreads();
    return r;
}

// ---------------------------------------------------------------------------
// Encode: fourier(a),fourier(b) -> @Win + bias -> LN -> GELU, for 256 uniques
// (block 0 also zeroes the tile counters for layer 0's router)
// ---------------------------------------------------------------------------
__global__ void encode_kernel(const float* __restrict__ Win, const float* __restrict__ bin_,
                              const float* __restrict__ gin, const float* __restrict__ bln) {
    int u = blockIdx.x, tid = threadIdx.x;
    if (u == 0 && tid < NT) g_cnt[tid] = 0;
    __shared__ float feat[32];
    __shared__ float red[256];
    if (tid < 32) {
        int which  = tid >> 4;
        int idx    = tid & 15;
        int fi     = idx & 7;
        int is_cos = (idx >> 3) & 1;
        int val    = which ? (u & 15) : (u >> 4);
        float xn   = (float)val * 0.39269908169872414f;   // fp32(2*pi/16)
        float ang  = xn * exp2f((float)fi);
        double dd  = (double)ang;
        feat[tid]  = (float)(is_cos ? cos(dd) : sin(dd));
    }
    __syncthreads();
    float v[4];
    #pragma unroll
    for (int j = 0; j < 4; ++j) {
        int d = tid + 256*j;
        float acc = bin_[d];
        #pragma unroll
        for (int f = 0; f < 32; ++f) acc += feat[f] * Win[f*DIM + d];
        v[j] = acc;
    }
    float s = block_reduce_sum_256(v[0]+v[1]+v[2]+v[3], red);
    float m = s * (1.0f/DIM);
    float s2l = 0.f;
    #pragma unroll
    for (int j = 0; j < 4; ++j) { float t = v[j]-m; s2l += t*t; }
    float s2 = block_reduce_sum_256(s2l, red);
    float rs = rsqrtf(s2*(1.0f/DIM) + 1e-5f);
    #pragma unroll
    for (int j = 0; j < 4; ++j) {
        int d = tid + 256*j;
        float y = (v[j]-m)*rs*gin[d] + bln[d];
        g_X[u*DIM + d] = gelu_f(y);
    }
}

// ---------------------------------------------------------------------------
// Router: softmax(x @ Wr) -> top-4 -> per-tile compacted (row, gate) lists
// ---------------------------------------------------------------------------
__global__ void router_kernel(const float* __restrict__ Wr) {
    int r = blockIdx.x, tid = threadIdx.x;
    __shared__ float part[256];
    int t = tid & 15, seg = tid >> 4;
    const float* x = g_X + r*DIM;
    float p = 0.f;
    int base = seg*64;
    #pragma unroll 8
    for (int j = 0; j < 64; ++j) p += x[base+j] * Wr[(base+j)*NT + t];
    part[tid] = p;
    __syncthreads();
    if (tid < 16) {
        float lg = 0.f;
        #pragma unroll
        for (int s = 0; s < 16; ++s) lg += part[tid + (s<<4)];
        part[tid] = lg;
    }
    __syncthreads();
    if (tid == 0) {
        float lg[16], mx = -1e30f;
        #pragma unroll
        for (int i = 0; i < 16; ++i) { lg[i] = part[i]; mx = fmaxf(mx, lg[i]); }
        float pe[16], sum = 0.f;
        #pragma unroll
        for (int i = 0; i < 16; ++i) { pe[i] = expf(lg[i]-mx); sum += pe[i]; }
        float inv = 1.0f/sum;
        unsigned used = 0;
        for (int s = 0; s < 4; ++s) {
            int best = -1; float bv = -1e30f;
            #pragma unroll
            for (int i = 0; i < 16; ++i)
                if (!((used>>i)&1) && pe[i] > bv) { bv = pe[i]; best = i; }
            used |= 1u << best;
            int pos = atomicAdd(&g_cnt[best], 1);
            g_rows[best*UNQ + pos] = r;
            g_gate[best*UNQ + pos] = bv*inv;
            g_pairs[r*4 + s] = best*UNQ + pos;
        }
    }
}

// ---------------------------------------------------------------------------
// FFN GEMM v3: 32x128 tile, 4x4 microtile, cp.async double-buffered K=32.
// MODE 0: H[p] = gelu(X[row] @ W1[t] + b1[t])     (gathered rows)
// MODE 1: Y[p] = gate[p] * (H[p] @ W2[t] + b2[t]) (contiguous rows)
// ---------------------------------------------------------------------------
template<int MODE>
__global__ void __launch_bounds__(256, 3) ffn_kernel(const float* __restrict__ W,
                                                     const float* __restrict__ bias) {
    int t  = blockIdx.z, rc = blockIdx.y, cc = blockIdx.x;
    int cnt = g_cnt[t];
    if (rc*32 >= cnt) return;

    W += (size_t)t*DIM*DIM;

    __shared__ float Xs[2][32][32];
    __shared__ float Ws[2][32][128];
    __shared__ int   rows_s[32];
    __shared__ float gate_s[32];

    int tid = threadIdx.x;
    if (tid < 32) {
        int idx = rc*32 + tid;
        int ci  = (idx < cnt) ? idx : (cnt-1);
        if (MODE == 0) rows_s[tid] = g_rows[t*UNQ + ci];
        else {
            rows_s[tid] = t*UNQ + rc*32 + tid;
            gate_s[tid] = (idx < cnt) ? g_gate[t*UNQ + idx] : 0.f;
        }
    }
    __syncthreads();

    const float* src = (MODE == 0) ? g_X : g_H;
    int c0 = cc*128;

    // staging maps
    int li = tid >> 3, lkv = tid & 7;              // X: 32 rows x 8 float4
    const float* xsrc = src + (size_t)rows_s[li]*DIM + lkv*4;
    int wk[4], wc = tid & 31;
    #pragma unroll
    for (int q = 0; q < 4; ++q) wk[q] = (tid + q*256) >> 5;

    // prologue: stage tiles 0 and 1
    #pragma unroll
    for (int s = 0; s < 2; ++s) {
        int k0 = s*32;
        cp16(&Xs[s][li][lkv*4], xsrc + k0);
        #pragma unroll
        for (int q = 0; q < 4; ++q)
            cp16(&Ws[s][wk[q]][wc*4], &W[(size_t)(k0+wk[q])*DIM + c0 + wc*4]);
        cp_commit();
    }

    int rg = tid >> 5, cg = tid & 31;
    float acc[4][4];
    #pragma unroll
    for (int i = 0; i < 4; ++i)
        #pragma unroll
        for (int j = 0; j < 4; ++j) acc[i][j] = 0.f;

    const int NTILE = DIM/32;   // 32
    int buf = 0;
    for (int it = 0; it < NTILE; ++it) {
        if (it + 1 < NTILE) asm volatile("cp.async.wait_group 1;\n");
        else                asm volatile("cp.async.wait_group 0;\n");
        __syncthreads();

        const float (*Xc)[32]  = Xs[buf];
        const float (*Wc)[128] = Ws[buf];
        #pragma unroll
        for (int k = 0; k < 32; ++k) {
            float a0 = Xc[rg*4+0][k], a1 = Xc[rg*4+1][k];
            float a2 = Xc[rg*4+2][k], a3 = Xc[rg*4+3][k];
            float4 bv = *(const float4*)&Wc[k][cg*4];
            acc[0][0] += a0*bv.x; acc[0][1] += a0*bv.y; acc[0][2] += a0*bv.z; acc[0][3] += a0*bv.w;
            acc[1][0] += a1*bv.x; acc[1][1] += a1*bv.y; acc[1][2] += a1*bv.z; acc[1][3] += a1*bv.w;
            acc[2][0] += a2*bv.x; acc[2][1] += a2*bv.y; acc[2][2] += a2*bv.z; acc[2][3] += a2*bv.w;
            acc[3][0] += a3*bv.x; acc[3][1] += a3*bv.y; acc[3][2] += a3*bv.z; acc[3][3] += a3*bv.w;
        }
        __syncthreads();

        if (it + 2 < NTILE) {
            int k0 = (it+2)*32;
            cp16(&Xs[buf][li][lkv*4], xsrc + k0);
            #pragma unroll
            for (int q = 0; q < 4; ++q)
                cp16(&Ws[buf][wk[q]][wc*4], &W[(size_t)(k0+wk[q])*DIM + c0 + wc*4]);
            cp_commit();
        }
        buf ^= 1;
    }

    int pbase = t*UNQ + rc*32;
    float bvals[4];
    #pragma unroll
    for (int j = 0; j < 4; ++j) bvals[j] = bias[t*DIM + c0 + cg*4 + j];

    #pragma unroll
    for (int i = 0; i < 4; ++i) {
        int lr = rg*4 + i;
        float v0 = acc[i][0]+bvals[0], v1 = acc[i][1]+bvals[1];
        float v2 = acc[i][2]+bvals[2], v3 = acc[i][3]+bvals[3];
        float4 o;
        if (MODE == 0) {
            o.x = gelu_f(v0); o.y = gelu_f(v1); o.z = gelu_f(v2); o.w = gelu_f(v3);
            *(float4*)&g_H[(size_t)(pbase+lr)*DIM + c0 + cg*4] = o;
        } else {
            float gt = gate_s[lr];
            o.x = v0*gt; o.y = v1*gt; o.z = v2*gt; o.w = v3*gt;
            *(float4*)&g_Y[(size_t)(pbase+lr)*DIM + c0 + cg*4] = o;
        }
    }
}

// ---------------------------------------------------------------------------
// Combine: x = LN(x + sum of the row's 4 gated expert outputs)
// (block 0 also zeroes tile counters for the NEXT layer's router)
// ---------------------------------------------------------------------------
__global__ void combine_kernel(const float* __restrict__ gl, const float* __restrict__ bl) {
    int r = blockIdx.x, tid = threadIdx.x;
    __shared__ float red[256];
    int p0 = g_pairs[r*4+0], p1 = g_pairs[r*4+1];
    int p2 = g_pairs[r*4+2], p3 = g_pairs[r*4+3];
    float v[4];
    #pragma unroll
    for (int j = 0; j < 4; ++j) {
        int d = tid + 256*j;
        v[j] = g_X[r*DIM+d]
             + g_Y[(size_t)p0*DIM+d] + g_Y[(size_t)p1*DIM+d]
             + g_Y[(size_t)p2*DIM+d] + g_Y[(size_t)p3*DIM+d];
    }
    if (r == 0 && tid < NT) g_cnt[tid] = 0;   // reset for next router
    float s = block_reduce_sum_256(v[0]+v[1]+v[2]+v[3], red);
    float m = s * (1.0f/DIM);
    float s2l = 0.f;
    #pragma unroll
    for (int j = 0; j < 4; ++j) { float t = v[j]-m; s2l += t*t; }
    float s2 = block_reduce_sum_256(s2l, red);
    float rs = rsqrtf(s2*(1.0f/DIM) + 1e-5f);
    #pragma unroll
    for (int j = 0; j < 4; ++j) {
        int d = tid + 256*j;
        g_X[r*DIM+d] = (v[j]-m)*rs*gl[d] + bl[d];
    }
}

// ---------------------------------------------------------------------------
// Heads stage 1 as tiled GEMM: g_HS[u, 0:512]  = gelu(x @ Ws1 + bs1)
//                              g_HS[u, 512:1024]= gelu(x @ Wd1 + bd1)
// ---------------------------------------------------------------------------
__global__ void headsA_kernel(const float* __restrict__ Ws1, const float* __restrict__ bs1,
                              const float* __restrict__ Wd1, const float* __restrict__ bd1) {
    int cc = blockIdx.x, rc = blockIdx.y;
    const float* W  = (cc < 4) ? Ws1 : Wd1;
    const float* bi = (cc < 4) ? bs1 : bd1;
    int c0     = (cc & 3) * 128;
    int outoff = (cc < 4) ? 0 : 512;

    __shared__ float Xs[32][32];
    __shared__ float Ws_[32][128];

    int tid = threadIdx.x;
    int rg = tid >> 5, cg = tid & 31;
    float acc[4][4];
    #pragma unroll
    for (int i = 0; i < 4; ++i)
        #pragma unroll
        for (int j = 0; j < 4; ++j) acc[i][j] = 0.f;

    int li = tid >> 3, lkv = tid & 7;

    for (int k0 = 0; k0 < DIM; k0 += 32) {
        *(float4*)&Xs[li][lkv*4] =
            *(const float4*)&g_X[(size_t)(rc*32+li)*DIM + k0 + lkv*4];
        #pragma unroll
        for (int q = 0; q < 4; ++q) {
            int e = tid + q*256;
            int k = e >> 5, cv = e & 31;
            *(float4*)&Ws_[k][cv*4] =
                *(const float4*)&W[(size_t)(k0+k)*512 + c0 + cv*4];
        }
        __syncthreads();
        #pragma unroll
        for (int k = 0; k < 32; ++k) {
            float a0 = Xs[rg*4+0][k], a1 = Xs[rg*4+1][k];
            float a2 = Xs[rg*4+2][k], a3 = Xs[rg*4+3][k];
            float4 bv = *(const float4*)&Ws_[k][cg*4];
            acc[0][0] += a0*bv.x; acc[0][1] += a0*bv.y; acc[0][2] += a0*bv.z; acc[0][3] += a0*bv.w;
            acc[1][0] += a1*bv.x; acc[1][1] += a1*bv.y; acc[1][2] += a1*bv.z; acc[1][3] += a1*bv.w;
            acc[2][0] += a2*bv.x; acc[2][1] += a2*bv.y; acc[2][2] += a2*bv.z; acc[2][3] += a2*bv.w;
            acc[3][0] += a3*bv.x; acc[3][1] += a3*bv.y; acc[3][2] += a3*bv.z; acc[3][3] += a3*bv.w;
        }
        __syncthreads();
    }

    float bvals[4];
    #pragma unroll
    for (int j = 0; j < 4; ++j) bvals[j] = bi[c0 + cg*4 + j];
    #pragma unroll
    for (int i = 0; i < 4; ++i) {
        int row = rc*32 + rg*4 + i;
        float4 o;
        o.x = gelu_f(acc[i][0]+bvals[0]);
        o.y = gelu_f(acc[i][1]+bvals[1]);
        o.z = gelu_f(acc[i][2]+bvals[2]);
        o.w = gelu_f(acc[i][3]+bvals[3]);
        *(float4*)&g_HS[(size_t)row*DIM + outoff + c0 + cg*4] = o;
    }
}

// ---------------------------------------------------------------------------
// Heads stage 2: table[u] = [hs @ Ws2 + bs2 , hd @ Wd2 + bd2]
// ---------------------------------------------------------------------------
__global__ void headsB_kernel(const float* __restrict__ Ws2, const float* __restrict__ bs2,
                              const float* __restrict__ Wd2, const float* __restrict__ bd2) {
    int u = blockIdx.x, tid = threadIdx.x;
    __shared__ float h[DIM];
    #pragma unroll
    for (int j = 0; j < 4; ++j) h[tid+256*j] = g_HS[(size_t)u*DIM + tid + 256*j];
    __syncthreads();
    if (tid < 5) {
        float o = bs2[tid];
        for (int k = 0; k < 512; ++k) o += h[k]*Ws2[k*5 + tid];
        g_table[u*11 + tid] = o;
    } else if (tid < 11) {
        int j = tid - 5;
        float o = bd2[j];
        for (int k = 0; k < 512; ++k) o += h[512+k]*Wd2[k*6 + j];
        g_table[u*11 + tid] = o;
    }
}

// ---------------------------------------------------------------------------
// Scatter table rows back to the full batch
// ---------------------------------------------------------------------------
__global__ void scatter_kernel(const int* __restrict__ a, const int* __restrict__ b,
                               float* __restrict__ out) {
    int idx = blockIdx.x*blockDim.x + threadIdx.x;
    if (idx >= BATCH*11) return;
    int i = idx / 11;
    int j = idx - i*11;
    int u = a[i]*16 + b[i];
    out[idx] = g_table[u*11 + j];
}

// ---------------------------------------------------------------------------
extern "C" void kernel_launch(void* const* d_in, const int* in_sizes, int n_in,
                              void* d_out, int out_size) {
    const int*   a    = (const int*)  d_in[0];
    const int*   b    = (const int*)  d_in[1];
    const float* Win  = (const float*)d_in[2];
    const float* bin_ = (const float*)d_in[3];
    const float* g_in = (const float*)d_in[4];
    const float* bln  = (const float*)d_in[5];
    const float* Wr   = (const float*)d_in[6];
    const float* W1   = (const float*)d_in[7];
    const float* b1   = (const float*)d_in[8];
    const float* W2   = (const float*)d_in[9];
    const float* b2   = (const float*)d_in[10];
    const float* g_l  = (const float*)d_in[11];
    const float* b_l  = (const float*)d_in[12];
    const float* Ws1  = (const float*)d_in[13];
    const float* bs1  = (const float*)d_in[14];
    const float* Ws2  = (const float*)d_in[15];
    const float* bs2  = (const float*)d_in[16];
    const float* Wd1  = (const float*)d_in[17];
    const float* bd1  = (const float*)d_in[18];
    const float* Wd2  = (const float*)d_in[19];
    const float* bd2  = (const float*)d_in[20];
    float* out = (float*)d_out;

    encode_kernel<<<UNQ, 256>>>(Win, bin_, g_in, bln);
    for (int l = 0; l < 3; ++l) {
        router_kernel<<<UNQ, 256>>>(Wr + (size_t)l*DIM*NT);
        ffn_kernel<0><<<dim3(8, 8, 16), 256>>>(W1 + (size_t)l*NT*DIM*DIM,
                                               b1 + (size_t)l*NT*DIM);
        ffn_kernel<1><<<dim3(8, 8, 16), 256>>>(W2 + (size_t)l*NT*DIM*DIM,
                                               b2 + (size_t)l*NT*DIM);
        combine_kernel<<<UNQ, 256>>>(g_l + (size_t)l*DIM, b_l + (size_t)l*DIM);
    }
    headsA_kernel<<<dim3(8, 8), 256>>>(Ws1, bs1, Wd1, bd1);
    headsB_kernel<<<UNQ, 256>>>(Ws2, bs2, Wd2, bd2);
    scatter_kernel<<<(BATCH*11 + 255)/256, 256>>>(a, b, out);
}

// round 8
// speedup vs baseline: 4.7297x; 1.4047x over previous
#include <cuda_runtime.h>
#include <math.h>
#include <stdint.h>

#define UNQ   256
#define DIM   1024
#define NT    16
#define BATCH 16384

static __device__ float g_X[UNQ*DIM];
static __device__ float g_H[NT*UNQ*DIM];
static __device__ float g_Y[NT*UNQ*DIM];
static __device__ float g_HS[UNQ*DIM];
static __device__ int   g_cnt[NT];
static __device__ int   g_rows[NT*UNQ];
static __device__ float g_gate[NT*UNQ];
static __device__ int   g_pairs[UNQ*4];
static __device__ float g_table[UNQ*11];

__device__ __forceinline__ float gelu_f(float x) {
    return 0.5f * x * (1.0f + erff(x * 0.70710678118654752f));
}

__device__ __forceinline__ void cp16(void* smem, const void* gmem) {
    unsigned s = (unsigned)__cvta_generic_to_shared(smem);
    asm volatile("cp.async.cg.shared.global [%0], [%1], 16;\n" :: "r"(s), "l"(gmem));
}
__device__ __forceinline__ void cp_commit() {
    asm volatile("cp.async.commit_group;\n");
}

__device__ __forceinline__ uint32_t to_tf32(float x) {
    uint32_t r;
    asm("cvt.rna.tf32.f32 %0, %1;" : "=r"(r) : "f"(x));
    return r;
}

__device__ __forceinline__ void mma_tf32(float* acc, uint32_t a0, uint32_t a1,
                                         uint32_t a2, uint32_t a3,
                                         uint32_t b0, uint32_t b1) {
    asm volatile(
        "mma.sync.aligned.m16n8k8.row.col.f32.tf32.tf32.f32 "
        "{%0,%1,%2,%3}, {%4,%5,%6,%7}, {%8,%9}, {%0,%1,%2,%3};"
        : "+f"(acc[0]), "+f"(acc[1]), "+f"(acc[2]), "+f"(acc[3])
        : "r"(a0), "r"(a1), "r"(a2), "r"(a3), "r"(b0), "r"(b1));
}

__device__ __forceinline__ float block_reduce_sum_256(float v, float* red) {
    int tid = threadIdx.x;
    red[tid] = v;
    __syncthreads();
    #pragma unroll
    for (int s = 128; s > 0; s >>= 1) {
        if (tid < s) red[tid] += red[tid + s];
        __syncthreads();
    }
    float r = red[0];
    __syncthreads();
    return r;
}

// ---------------------------------------------------------------------------
// Encode: fourier(a),fourier(b) -> @Win + bias -> LN -> GELU, for 256 uniques
// ---------------------------------------------------------------------------
__global__ void encode_kernel(const float* __restrict__ Win, const float* __restrict__ bin_,
                              const float* __restrict__ gin, const float* __restrict__ bln) {
    int u = blockIdx.x, tid = threadIdx.x;
    if (u == 0 && tid < NT) g_cnt[tid] = 0;
    __shared__ float feat[32];
    __shared__ float red[256];
    if (tid < 32) {
        int which  = tid >> 4;
        int idx    = tid & 15;
        int fi     = idx & 7;
        int is_cos = (idx >> 3) & 1;
        int val    = which ? (u & 15) : (u >> 4);
        float xn   = (float)val * 0.39269908169872414f;   // fp32(2*pi/16)
        float ang  = xn * exp2f((float)fi);
        double dd  = (double)ang;
        feat[tid]  = (float)(is_cos ? cos(dd) : sin(dd));
    }
    __syncthreads();
    float v[4];
    #pragma unroll
    for (int j = 0; j < 4; ++j) {
        int d = tid + 256*j;
        float acc = bin_[d];
        #pragma unroll
        for (int f = 0; f < 32; ++f) acc += feat[f] * Win[f*DIM + d];
        v[j] = acc;
    }
    float s = block_reduce_sum_256(v[0]+v[1]+v[2]+v[3], red);
    float m = s * (1.0f/DIM);
    float s2l = 0.f;
    #pragma unroll
    for (int j = 0; j < 4; ++j) { float t = v[j]-m; s2l += t*t; }
    float s2 = block_reduce_sum_256(s2l, red);
    float rs = rsqrtf(s2*(1.0f/DIM) + 1e-5f);
    #pragma unroll
    for (int j = 0; j < 4; ++j) {
        int d = tid + 256*j;
        float y = (v[j]-m)*rs*gin[d] + bln[d];
        g_X[u*DIM + d] = gelu_f(y);
    }
}

// ---------------------------------------------------------------------------
// Router: softmax(x @ Wr) -> top-4 -> per-tile compacted (row, gate) lists
// ---------------------------------------------------------------------------
__global__ void router_kernel(const float* __restrict__ Wr) {
    int r = blockIdx.x, tid = threadIdx.x;
    __shared__ float part[256];
    int t = tid & 15, seg = tid >> 4;
    const float* x = g_X + r*DIM;
    float p = 0.f;
    int base = seg*64;
    #pragma unroll 8
    for (int j = 0; j < 64; ++j) p += x[base+j] * Wr[(base+j)*NT + t];
    part[tid] = p;
    __syncthreads();
    if (tid < 16) {
        float lg = 0.f;
        #pragma unroll
        for (int s = 0; s < 16; ++s) lg += part[tid + (s<<4)];
        part[tid] = lg;
    }
    __syncthreads();
    if (tid == 0) {
        float lg[16], mx = -1e30f;
        #pragma unroll
        for (int i = 0; i < 16; ++i) { lg[i] = part[i]; mx = fmaxf(mx, lg[i]); }
        float pe[16], sum = 0.f;
        #pragma unroll
        for (int i = 0; i < 16; ++i) { pe[i] = expf(lg[i]-mx); sum += pe[i]; }
        float inv = 1.0f/sum;
        unsigned used = 0;
        for (int s = 0; s < 4; ++s) {
            int best = -1; float bv = -1e30f;
            #pragma unroll
            for (int i = 0; i < 16; ++i)
                if (!((used>>i)&1) && pe[i] > bv) { bv = pe[i]; best = i; }
            used |= 1u << best;
            int pos = atomicAdd(&g_cnt[best], 1);
            g_rows[best*UNQ + pos] = r;
            g_gate[best*UNQ + pos] = bv*inv;
            g_pairs[r*4 + s] = best*UNQ + pos;
        }
    }
}

// ---------------------------------------------------------------------------
// FFN GEMM v4: TF32 mma.sync.m16n8k8, 32x128 tile, cp.async double-buffer K=32
// MODE 0: H[p] = gelu(X[row] @ W1[t] + b1[t])     (gathered rows)
// MODE 1: Y[p] = gate[p] * (H[p] @ W2[t] + b2[t]) (contiguous rows)
// ---------------------------------------------------------------------------
#define XPITCH 36
#define WPITCH 136

template<int MODE>
__global__ void __launch_bounds__(256) ffn_kernel(const float* __restrict__ W,
                                                  const float* __restrict__ bias) {
    int t  = blockIdx.z, rc = blockIdx.y, cc = blockIdx.x;
    int cnt = g_cnt[t];
    if (rc*32 >= cnt) return;

    W += (size_t)t*DIM*DIM;

    __shared__ float Xs[2][32][XPITCH];
    __shared__ float Ws[2][32][WPITCH];
    __shared__ int   rows_s[32];
    __shared__ float gate_s[32];

    int tid = threadIdx.x;
    if (tid < 32) {
        int idx = rc*32 + tid;
        int ci  = (idx < cnt) ? idx : (cnt-1);
        if (MODE == 0) rows_s[tid] = g_rows[t*UNQ + ci];
        else {
            rows_s[tid] = t*UNQ + rc*32 + tid;
            gate_s[tid] = (idx < cnt) ? g_gate[t*UNQ + idx] : 0.f;
        }
    }
    __syncthreads();

    const float* src = (MODE == 0) ? g_X : g_H;
    int c0 = cc*128;

    // staging maps
    int li = tid >> 3, lkv = tid & 7;              // X: 32 rows x 8 float4
    const float* xsrc = src + (size_t)rows_s[li]*DIM + lkv*4;
    int wk[4], wc = tid & 31;
    #pragma unroll
    for (int q = 0; q < 4; ++q) wk[q] = (tid + q*256) >> 5;

    // prologue: stage tiles 0 and 1
    #pragma unroll
    for (int s = 0; s < 2; ++s) {
        int k0 = s*32;
        cp16(&Xs[s][li][lkv*4], xsrc + k0);
        #pragma unroll
        for (int q = 0; q < 4; ++q)
            cp16(&Ws[s][wk[q]][wc*4], &W[(size_t)(k0+wk[q])*DIM + c0 + wc*4]);
        cp_commit();
    }

    // warp tiling: warp w -> row half r (16 rows), col quarter cq (32 cols)
    int w  = tid >> 5, l = tid & 31;
    int g  = l >> 2, tig = l & 3;
    int r  = w & 1, cq = w >> 1;
    int rb = r*16;

    float acc[4][4];
    #pragma unroll
    for (int i = 0; i < 4; ++i)
        #pragma unroll
        for (int j = 0; j < 4; ++j) acc[i][j] = 0.f;

    const int NTILE = DIM/32;   // 32
    int buf = 0;
    for (int it = 0; it < NTILE; ++it) {
        if (it + 1 < NTILE) asm volatile("cp.async.wait_group 1;\n");
        else                asm volatile("cp.async.wait_group 0;\n");
        __syncthreads();

        const float (*Xc)[XPITCH] = Xs[buf];
        const float (*Wc)[WPITCH] = Ws[buf];
        #pragma unroll
        for (int kk = 0; kk < 4; ++kk) {
            int k0 = kk*8;
            uint32_t a0 = to_tf32(Xc[rb + g     ][k0 + tig    ]);
            uint32_t a1 = to_tf32(Xc[rb + g + 8 ][k0 + tig    ]);
            uint32_t a2 = to_tf32(Xc[rb + g     ][k0 + tig + 4]);
            uint32_t a3 = to_tf32(Xc[rb + g + 8 ][k0 + tig + 4]);
            #pragma unroll
            for (int nt = 0; nt < 4; ++nt) {
                int col = cq*32 + nt*8 + g;
                uint32_t b0 = to_tf32(Wc[k0 + tig    ][col]);
                uint32_t b1 = to_tf32(Wc[k0 + tig + 4][col]);
                mma_tf32(acc[nt], a0, a1, a2, a3, b0, b1);
            }
        }
        __syncthreads();

        if (it + 2 < NTILE) {
            int k0 = (it+2)*32;
            cp16(&Xs[buf][li][lkv*4], xsrc + k0);
            #pragma unroll
            for (int q = 0; q < 4; ++q)
                cp16(&Ws[buf][wk[q]][wc*4], &W[(size_t)(k0+wk[q])*DIM + c0 + wc*4]);
            cp_commit();
        }
        buf ^= 1;
    }

    // epilogue: C frag -> rows rb+g / rb+g+8, cols cq*32+nt*8+2*tig(+1)
    int pbase = t*UNQ + rc*32;
    int row0 = rb + g, row1 = rb + g + 8;
    #pragma unroll
    for (int nt = 0; nt < 4; ++nt) {
        int colb = cq*32 + nt*8 + 2*tig;
        float bv0 = bias[t*DIM + c0 + colb];
        float bv1 = bias[t*DIM + c0 + colb + 1];
        float v00 = acc[nt][0] + bv0, v01 = acc[nt][1] + bv1;   // row0
        float v10 = acc[nt][2] + bv0, v11 = acc[nt][3] + bv1;   // row1
        if (MODE == 0) {
            float2 o0 = { gelu_f(v00), gelu_f(v01) };
            float2 o1 = { gelu_f(v10), gelu_f(v11) };
            *(float2*)&g_H[(size_t)(pbase+row0)*DIM + c0 + colb] = o0;
            *(float2*)&g_H[(size_t)(pbase+row1)*DIM + c0 + colb] = o1;
        } else {
            float g0 = gate_s[row0], g1 = gate_s[row1];
            float2 o0 = { v00*g0, v01*g0 };
            float2 o1 = { v10*g1, v11*g1 };
            *(float2*)&g_Y[(size_t)(pbase+row0)*DIM + c0 + colb] = o0;
            *(float2*)&g_Y[(size_t)(pbase+row1)*DIM + c0 + colb] = o1;
        }
    }
}

// ---------------------------------------------------------------------------
// Combine: x = LN(x + sum of the row's 4 gated expert outputs)
// (row 0 also zeroes tile counters for the NEXT layer's router)
// ---------------------------------------------------------------------------
__global__ void combine_kernel(const float* __restrict__ gl, const float* __restrict__ bl) {
    int r = blockIdx.x, tid = threadIdx.x;
    __shared__ float red[256];
    int p0 = g_pairs[r*4+0], p1 = g_pairs[r*4+1];
    int p2 = g_pairs[r*4+2], p3 = g_pairs[r*4+3];
    float v[4];
    #pragma unroll
    for (int j = 0; j < 4; ++j) {
        int d = tid + 256*j;
        v[j] = g_X[r*DIM+d]
             + g_Y[(size_t)p0*DIM+d] + g_Y[(size_t)p1*DIM+d]
             + g_Y[(size_t)p2*DIM+d] + g_Y[(size_t)p3*DIM+d];
    }
    if (r == 0 && tid < NT) g_cnt[tid] = 0;   // reset for next router
    float s = block_reduce_sum_256(v[0]+v[1]+v[2]+v[3], red);
    float m = s * (1.0f/DIM);
    float s2l = 0.f;
    #pragma unroll
    for (int j = 0; j < 4; ++j) { float t = v[j]-m; s2l += t*t; }
    float s2 = block_reduce_sum_256(s2l, red);
    float rs = rsqrtf(s2*(1.0f/DIM) + 1e-5f);
    #pragma unroll
    for (int j = 0; j < 4; ++j) {
        int d = tid + 256*j;
        g_X[r*DIM+d] = (v[j]-m)*rs*gl[d] + bl[d];
    }
}

// ---------------------------------------------------------------------------
// Heads stage 1 as tiled GEMM: g_HS[u, 0:512]  = gelu(x @ Ws1 + bs1)
//                              g_HS[u, 512:1024]= gelu(x @ Wd1 + bd1)
// ---------------------------------------------------------------------------
__global__ void headsA_kernel(const float* __restrict__ Ws1, const float* __restrict__ bs1,
                              const float* __restrict__ Wd1, const float* __restrict__ bd1) {
    int cc = blockIdx.x, rc = blockIdx.y;
    const float* W  = (cc < 4) ? Ws1 : Wd1;
    const float* bi = (cc < 4) ? bs1 : bd1;
    int c0     = (cc & 3) * 128;
    int outoff = (cc < 4) ? 0 : 512;

    __shared__ float Xs[32][32];
    __shared__ float Ws_[32][128];

    int tid = threadIdx.x;
    int rg = tid >> 5, cg = tid & 31;
    float acc[4][4];
    #pragma unroll
    for (int i = 0; i < 4; ++i)
        #pragma unroll
        for (int j = 0; j < 4; ++j) acc[i][j] = 0.f;

    int li = tid >> 3, lkv = tid & 7;

    for (int k0 = 0; k0 < DIM; k0 += 32) {
        *(float4*)&Xs[li][lkv*4] =
            *(const float4*)&g_X[(size_t)(rc*32+li)*DIM + k0 + lkv*4];
        #pragma unroll
        for (int q = 0; q < 4; ++q) {
            int e = tid + q*256;
            int k = e >> 5, cv = e & 31;
            *(float4*)&Ws_[k][cv*4] =
                *(const float4*)&W[(size_t)(k0+k)*512 + c0 + cv*4];
        }
        __syncthreads();
        #pragma unroll
        for (int k = 0; k < 32; ++k) {
            float a0 = Xs[rg*4+0][k], a1 = Xs[rg*4+1][k];
            float a2 = Xs[rg*4+2][k], a3 = Xs[rg*4+3][k];
            float4 bv = *(const float4*)&Ws_[k][cg*4];
            acc[0][0] += a0*bv.x; acc[0][1] += a0*bv.y; acc[0][2] += a0*bv.z; acc[0][3] += a0*bv.w;
            acc[1][0] += a1*bv.x; acc[1][1] += a1*bv.y; acc[1][2] += a1*bv.z; acc[1][3] += a1*bv.w;
            acc[2][0] += a2*bv.x; acc[2][1] += a2*bv.y; acc[2][2] += a2*bv.z; acc[2][3] += a2*bv.w;
            acc[3][0] += a3*bv.x; acc[3][1] += a3*bv.y; acc[3][2] += a3*bv.z; acc[3][3] += a3*bv.w;
        }
        __syncthreads();
    }

    float bvals[4];
    #pragma unroll
    for (int j = 0; j < 4; ++j) bvals[j] = bi[c0 + cg*4 + j];
    #pragma unroll
    for (int i = 0; i < 4; ++i) {
        int row = rc*32 + rg*4 + i;
        float4 o;
        o.x = gelu_f(acc[i][0]+bvals[0]);
        o.y = gelu_f(acc[i][1]+bvals[1]);
        o.z = gelu_f(acc[i][2]+bvals[2]);
        o.w = gelu_f(acc[i][3]+bvals[3]);
        *(float4*)&g_HS[(size_t)row*DIM + outoff + c0 + cg*4] = o;
    }
}

// ---------------------------------------------------------------------------
// Heads stage 2: table[u] = [hs @ Ws2 + bs2 , hd @ Wd2 + bd2]
// ---------------------------------------------------------------------------
__global__ void headsB_kernel(const float* __restrict__ Ws2, const float* __restrict__ bs2,
                              const float* __restrict__ Wd2, const float* __restrict__ bd2) {
    int u = blockIdx.x, tid = threadIdx.x;
    __shared__ float h[DIM];
    #pragma unroll
    for (int j = 0; j < 4; ++j) h[tid+256*j] = g_HS[(size_t)u*DIM + tid + 256*j];
    __syncthreads();
    if (tid < 5) {
        float o = bs2[tid];
        for (int k = 0; k < 512; ++k) o += h[k]*Ws2[k*5 + tid];
        g_table[u*11 + tid] = o;
    } else if (tid < 11) {
        int j = tid - 5;
        float o = bd2[j];
        for (int k = 0; k < 512; ++k) o += h[512+k]*Wd2[k*6 + j];
        g_table[u*11 + tid] = o;
    }
}

// ---------------------------------------------------------------------------
// Scatter table rows back to the full batch
// ---------------------------------------------------------------------------
__global__ void scatter_kernel(const int* __restrict__ a, const int* __restrict__ b,
                               float* __restrict__ out) {
    int idx = blockIdx.x*blockDim.x + threadIdx.x;
    if (idx >= BATCH*11) return;
    int i = idx / 11;
    int j = idx - i*11;
    int u = a[i]*16 + b[i];
    out[idx] = g_table[u*11 + j];
}

// ---------------------------------------------------------------------------
extern "C" void kernel_launch(void* const* d_in, const int* in_sizes, int n_in,
                              void* d_out, int out_size) {
    const int*   a    = (const int*)  d_in[0];
    const int*   b    = (const int*)  d_in[1];
    const float* Win  = (const float*)d_in[2];
    const float* bin_ = (const float*)d_in[3];
    const float* g_in = (const float*)d_in[4];
    const float* bln  = (const float*)d_in[5];
    const float* Wr   = (const float*)d_in[6];
    const float* W1   = (const float*)d_in[7];
    const float* b1   = (const float*)d_in[8];
    const float* W2   = (const float*)d_in[9];
    const float* b2   = (const float*)d_in[10];
    const float* g_l  = (const float*)d_in[11];
    const float* b_l  = (const float*)d_in[12];
    const float* Ws1  = (const float*)d_in[13];
    const float* bs1  = (const float*)d_in[14];
    const float* Ws2  = (const float*)d_in[15];
    const float* bs2  = (const float*)d_in[16];
    const float* Wd1  = (const float*)d_in[17];
    const float* bd1  = (const float*)d_in[18];
    const float* Wd2  = (const float*)d_in[19];
    const float* bd2  = (const float*)d_in[20];
    float* out = (float*)d_out;

    encode_kernel<<<UNQ, 256>>>(Win, bin_, g_in, bln);
    for (int l = 0; l < 3; ++l) {
        router_kernel<<<UNQ, 256>>>(Wr + (size_t)l*DIM*NT);
        ffn_kernel<0><<<dim3(8, 8, 16), 256>>>(W1 + (size_t)l*NT*DIM*DIM,
                                               b1 + (size_t)l*NT*DIM);
        ffn_kernel<1><<<dim3(8, 8, 16), 256>>>(W2 + (size_t)l*NT*DIM*DIM,
                                               b2 + (size_t)l*NT*DIM);
        combine_kernel<<<UNQ, 256>>>(g_l + (size_t)l*DIM, b_l + (size_t)l*DIM);
    }
    headsA_kernel<<<dim3(8, 8), 256>>>(Ws1, bs1, Wd1, bd1);
    headsB_kernel<<<UNQ, 256>>>(Ws2, bs2, Wd2, bd2);
    scatter_kernel<<<(BATCH*11 + 255)/256, 256>>>(a, b, out);
}